// round 11
// baseline (speedup 1.0000x reference)
#include <cuda_runtime.h>
#include <cstdint>

#define LRELU(v) ((v) > 0.0f ? (v) : 0.01f * (v))
using ull = unsigned long long;

static constexpr int Bb   = 512;
static constexpr int Nn   = 64;
static constexpr int Hh   = 4;
static constexpr int FOUT = 16;

// Scratch for inter-stage activations (x1, x2: [B, N, 128])
__device__ float g_x1[(size_t)Bb * Nn * 128];
__device__ float g_x2[(size_t)Bb * Nn * 128];

// ---------------------------------------------------------------------------
// Packed fp32x2 helpers (Blackwell FFMA2 — only reachable via PTX)
// ---------------------------------------------------------------------------
__device__ __forceinline__ ull pack2(float a, float b) {
    ull r;
    asm("mov.b64 %0, {%1, %2};" : "=l"(r) : "f"(a), "f"(b));
    return r;
}
__device__ __forceinline__ void unpack2(ull v, float& a, float& b) {
    asm("mov.b64 {%0, %1}, %2;" : "=f"(a), "=f"(b) : "l"(v));
}
__device__ __forceinline__ ull fma2(ull a, ull b, ull c) {
    ull d;
    asm("fma.rn.f32x2 %0, %1, %2, %3;" : "=l"(d) : "l"(a), "l"(b), "l"(c));
    return d;
}

// ---------------------------------------------------------------------------
// cp.async helpers
// ---------------------------------------------------------------------------
__device__ __forceinline__ uint32_t s2u(const void* p) {
    return (uint32_t)__cvta_generic_to_shared(p);
}
__device__ __forceinline__ void cp4(uint32_t dst, const float* src) {
    asm volatile("cp.async.ca.shared.global [%0], [%1], 4;" :: "r"(dst), "l"(src));
}
__device__ __forceinline__ void cp_commit() {
    asm volatile("cp.async.commit_group;" ::: "memory");
}
template<int N>
__device__ __forceinline__ void cp_wait() {
    asm volatile("cp.async.wait_group %0;" :: "n"(N) : "memory");
}

// ---------------------------------------------------------------------------
// Register-blocked packed GEMM: C[64][NC] = A(smem)[64][K] * W(gmem)[NC][K]^T + b
// 512 threads. Thread grid: G col-groups (tx), 512/G row-groups (ty);
// micro-tile RPT rows x CW=NC/G cols (CW=2 -> one f32x2 pair, LDS.64 B per kk).
//   Main GEMMs: G=64, RPT=8 -> warp-uniform ty, A-loads pure broadcasts.
// W k-tiles staged transposed [kk][n] (stride 132) via double-buffered cp.async.
// ---------------------------------------------------------------------------
template<int NC, int RPT, int G>
__device__ __forceinline__ void gemm(
    const float* __restrict__ sA, int lda, int Kdim,
    const float* __restrict__ gW, const float* __restrict__ gBias,
    float* __restrict__ sWt,              // 2 buffers of 32*132 floats
    float* __restrict__ sOut, int ldo, bool outT, bool relu, int tid)
{
    constexpr int CW = NC / G;            // cols per thread (== 2)
    static_assert(CW == 2, "one pair per thread");
    const int tx = tid % G, ty = tid / G;

    ull acc[RPT];
#pragma unroll
    for (int i = 0; i < RPT; ++i) acc[i] = 0ull;

    const int kk = tid & 31;
    const int n0 = tid >> 5;               // 0..15
    const int ntiles = Kdim / 32;

    // stage tile t into buffer buf (transposed [kk][n])
    auto stage = [&](int t, int buf) {
        float* dst = sWt + buf * (32 * 132) + kk * 132;
        const float* src = gW + (size_t)t * 32 + kk;
#pragma unroll
        for (int n = n0; n < NC; n += 16)
            cp4(s2u(dst + n), src + (size_t)n * Kdim);
        cp_commit();
    };

    stage(0, 0);
    for (int t = 0; t < ntiles; ++t) {
        if (t + 1 < ntiles) { stage(t + 1, (t + 1) & 1); cp_wait<1>(); }
        else                { cp_wait<0>(); }
        __syncthreads();                   // tile t ready; fences prior phase smem
        const float* w  = sWt + (t & 1) * (32 * 132);
        const float* ar = sA + (RPT * ty) * lda + t * 32;
#pragma unroll 4
        for (int k4 = 0; k4 < 8; ++k4) {
            float4 a[RPT];
#pragma unroll
            for (int r = 0; r < RPT; ++r)
                a[r] = *(const float4*)(ar + r * lda + 4 * k4);   // broadcast
#pragma unroll
            for (int q = 0; q < 4; ++q) {
                ull bb = *(const ull*)(w + (4 * k4 + q) * 132 + 2 * tx);
#pragma unroll
                for (int r = 0; r < RPT; ++r)
                    acc[r] = fma2(pack2((&a[r].x)[q], (&a[r].x)[q]), bb, acc[r]);
            }
        }
        __syncthreads();                   // safe to overwrite buffer t&1
    }

    // epilogue
    {
        int col = 2 * tx;
        float b0 = gBias[col], b1 = gBias[col + 1];
#pragma unroll
        for (int i = 0; i < RPT; ++i) {
            float v0, v1; unpack2(acc[i], v0, v1);
            v0 += b0; v1 += b1;
            if (relu) { v0 = LRELU(v0); v1 = LRELU(v1); }
            int row = RPT * ty + i;
            if (outT) { sOut[col * ldo + row] = v0; sOut[(col + 1) * ldo + row] = v1; }
            else      { sOut[row * ldo + col] = v0; sOut[row * ldo + col + 1]   = v1; }
        }
    }
}

// ---------------------------------------------------------------------------
// Fused attention block: one CTA (512 threads) per (head h, batch b).
// ---------------------------------------------------------------------------
template<int IN_DIM>
__global__ void __launch_bounds__(512, 1)
attn_kernel(const float* __restrict__ x,
            const float* __restrict__ Ew, const float* __restrict__ Eb,
            const float* __restrict__ Kw, const float* __restrict__ Kb,
            const float* __restrict__ Qw, const float* __restrict__ Qb,
            const float* __restrict__ Vw, const float* __restrict__ Vb,
            float* __restrict__ w_out, float* __restrict__ x_out)
{
    extern __shared__ float smem[];
    const int h = blockIdx.x, b = blockIdx.y;
    const int tid = threadIdx.x;

    float* s_x  = smem;                     // 64*IN_DIM (reused as s_w later)
    float* s_se = s_x  + 64 * IN_DIM;       // 64*128
    float* s_kT = s_se + 64 * 128;          // 128*68  (k^T: [e][m])
    float* s_q  = s_kT + 128 * 68;          // 64*128
    float* s_v  = s_q  + 64 * 128;          // 64*32
    float* s_wt = s_v  + 64 * 32;           // 2 * 32*132 staging
    float* s_w  = s_x;                      // 64*64 overlay

    // Load input tile x[b] (coalesced float4); fenced by gemm's first barrier.
    const float* gx = x + (size_t)b * 64 * IN_DIM;
    for (int i = 4 * tid; i < 64 * IN_DIM; i += 2048)
        *(float4*)&s_x[i] = *(const float4*)&gx[i];

    // Phase 1: se = lrelu(x @ Ew^T + Eb)   (8 rows x 2 cols per thread)
    gemm<128, 8, 64>(s_x, IN_DIM, IN_DIM,
                     Ew + (size_t)h * 128 * IN_DIM, Eb + h * 128,
                     s_wt, s_se, 128, false, true, tid);
    // Phase 2: k^T, q (8x2), v (2x2)
    gemm<128, 8, 64>(s_se, 128, 128, Kw + (size_t)h * 128 * 128, Kb + h * 128,
                     s_wt, s_kT, 68, true, false, tid);
    gemm<128, 8, 64>(s_se, 128, 128, Qw + (size_t)h * 128 * 128, Qb + h * 128,
                     s_wt, s_q, 128, false, false, tid);
    gemm<32, 2, 16>(s_se, 128, 128, Vw + (size_t)h * 32 * 128, Vb + h * 32,
                    s_wt, s_v, 32, false, true, tid);
    __syncthreads();

    // Phase 3: scores (64x64, K=128) + row softmax.
    // Thread grid 32(tx) x 16(ty): 4 rows x 2 cols. A broadcast, B LDS.64.
    {
        const int tx = tid & 31, ty = tid >> 5;
        ull sacc[4] = {0ull, 0ull, 0ull, 0ull};
#pragma unroll 4
        for (int k4 = 0; k4 < 32; ++k4) {
            float4 a[4];
#pragma unroll
            for (int r = 0; r < 4; ++r)
                a[r] = *(const float4*)&s_q[(4 * ty + r) * 128 + 4 * k4];
#pragma unroll
            for (int q = 0; q < 4; ++q) {
                ull bb = *(const ull*)&s_kT[(4 * k4 + q) * 68 + 2 * tx];
#pragma unroll
                for (int r = 0; r < 4; ++r)
                    sacc[r] = fma2(pack2((&a[r].x)[q], (&a[r].x)[q]), bb, sacc[r]);
            }
        }
        const float SCALE = 0.08838834764831845f;  // 1/sqrt(128)
        float* wg = w_out + (((size_t)h * Bb + b) * 64) * 64;
#pragma unroll
        for (int i = 0; i < 4; ++i) {
            float sc0, sc1; unpack2(sacc[i], sc0, sc1);
            sc0 *= SCALE; sc1 *= SCALE;
            float m = fmaxf(sc0, sc1);
#pragma unroll
            for (int off = 1; off < 32; off <<= 1)
                m = fmaxf(m, __shfl_xor_sync(0xffffffffu, m, off));
            sc0 = __expf(sc0 - m); sc1 = __expf(sc1 - m);
            float s = sc0 + sc1;
#pragma unroll
            for (int off = 1; off < 32; off <<= 1)
                s += __shfl_xor_sync(0xffffffffu, s, off);
            float inv = 1.0f / s;
            float2 wv = make_float2(sc0 * inv, sc1 * inv);
            int row = 4 * ty + i;
            *(float2*)&s_w[row * 64 + 2 * tx] = wv;
            *(float2*)&wg[(size_t)row * 64 + 2 * tx] = wv;
        }
    }
    __syncthreads();

    // Phase 4: att = w @ v (64x32, K=64). Thread grid 16(tx) x 32(ty): 2x2.
    {
        const int tx = tid & 15, ty = tid >> 4;
        ull aacc[2] = {0ull, 0ull};
#pragma unroll 4
        for (int k4 = 0; k4 < 16; ++k4) {
            float4 a0 = *(const float4*)&s_w[(2 * ty + 0) * 64 + 4 * k4];
            float4 a1 = *(const float4*)&s_w[(2 * ty + 1) * 64 + 4 * k4];
#pragma unroll
            for (int q = 0; q < 4; ++q) {
                ull bb = *(const ull*)&s_v[(4 * k4 + q) * 32 + 2 * tx];
                aacc[0] = fma2(pack2((&a0.x)[q], (&a0.x)[q]), bb, aacc[0]);
                aacc[1] = fma2(pack2((&a1.x)[q], (&a1.x)[q]), bb, aacc[1]);
            }
        }
#pragma unroll
        for (int i = 0; i < 2; ++i) {
            float v0, v1; unpack2(aacc[i], v0, v1);
            int row = 2 * ty + i;
            *(float2*)&x_out[((size_t)b * 64 + row) * 128 + h * 32 + 2 * tx] =
                make_float2(v0, v1);
        }
    }
}

// ---------------------------------------------------------------------------
// Final MLP + softmax policy head (~5% of runtime).
// ---------------------------------------------------------------------------
__global__ void __launch_bounds__(256)
mlp_kernel(const float* __restrict__ x,
           const float* __restrict__ F1w, const float* __restrict__ F1b,
           const float* __restrict__ F2w, const float* __restrict__ F2b,
           float* __restrict__ out)
{
    __shared__ float sF1[128 * 65];
    __shared__ float sF2[16 * 64];
    __shared__ float sB1[64];
    __shared__ float sB2[16];
    __shared__ float sx[8][2][128];

    const int tid = threadIdx.x, lane = tid & 31, warp = tid >> 5;

    for (int idx = tid; idx < 64 * 128; idx += 256) {
        int o = idx >> 7, d = idx & 127;
        sF1[d * 65 + o] = F1w[idx];
    }
    for (int idx = tid; idx < 16 * 64; idx += 256) sF2[idx] = F2w[idx];
    if (tid < 64) sB1[tid] = F1b[tid];
    if (tid < 16) sB2[tid] = F2b[tid];
    __syncthreads();

    const int NGRP = (Bb * Nn) / 2;
    for (int g = blockIdx.x * 8 + warp; g < NGRP; g += gridDim.x * 8) {
        int row0 = g * 2;
#pragma unroll
        for (int r = 0; r < 2; ++r)
            *(float4*)&sx[warp][r][lane * 4] =
                *(const float4*)&x[(size_t)(row0 + r) * 128 + lane * 4];
        __syncwarp();

        float h0[2], h1[2];
        h0[0] = h0[1] = sB1[lane];
        h1[0] = h1[1] = sB1[lane + 32];
#pragma unroll 8
        for (int d = 0; d < 128; ++d) {
            float w0 = sF1[d * 65 + lane];
            float w1 = sF1[d * 65 + 32 + lane];
#pragma unroll
            for (int r = 0; r < 2; ++r) {
                float xv = sx[warp][r][d];
                h0[r] = fmaf(xv, w0, h0[r]);
                h1[r] = fmaf(xv, w1, h1[r]);
            }
        }
#pragma unroll
        for (int r = 0; r < 2; ++r) { h0[r] = LRELU(h0[r]); h1[r] = LRELU(h1[r]); }

#pragma unroll
        for (int r = 0; r < 2; ++r) {
            float p[16];
#pragma unroll
            for (int j = 0; j < 16; ++j) {
                float t = fmaf(h0[r], sF2[j * 64 + lane],
                               h1[r] * sF2[j * 64 + 32 + lane]);
#pragma unroll
                for (int off = 16; off > 0; off >>= 1)
                    t += __shfl_xor_sync(0xffffffffu, t, off);
                p[j] = t + sB2[j];
            }
            float m = p[0];
#pragma unroll
            for (int j = 1; j < 16; ++j) m = fmaxf(m, p[j]);
            float s = 0.0f;
#pragma unroll
            for (int j = 0; j < 16; ++j) { p[j] = __expf(p[j] - m); s += p[j]; }
            float inv = 1.0f / s;
            float mine = 0.0f;
#pragma unroll
            for (int j = 0; j < 16; ++j) mine = (lane == j) ? p[j] * inv : mine;
            if (lane < 16) out[(size_t)(row0 + r) * 16 + lane] = mine;
        }
        __syncwarp();
    }
}

// ---------------------------------------------------------------------------
extern "C" void kernel_launch(void* const* d_in, const int* in_sizes, int n_in,
                              void* d_out, int out_size)
{
    const float* states = (const float*)d_in[0];
    const float* E1w = (const float*)d_in[1];  const float* E1b = (const float*)d_in[2];
    const float* K1w = (const float*)d_in[3];  const float* K1b = (const float*)d_in[4];
    const float* Q1w = (const float*)d_in[5];  const float* Q1b = (const float*)d_in[6];
    const float* V1w = (const float*)d_in[7];  const float* V1b = (const float*)d_in[8];
    const float* E2w = (const float*)d_in[9];  const float* E2b = (const float*)d_in[10];
    const float* K2w = (const float*)d_in[11]; const float* K2b = (const float*)d_in[12];
    const float* Q2w = (const float*)d_in[13]; const float* Q2b = (const float*)d_in[14];
    const float* V2w = (const float*)d_in[15]; const float* V2b = (const float*)d_in[16];
    const float* F1w = (const float*)d_in[17]; const float* F1b = (const float*)d_in[18];
    const float* F2w = (const float*)d_in[19]; const float* F2b = (const float*)d_in[20];

    float* out    = (float*)d_out;
    float* policy = out;                                      // [512,64,16]
    float* w1     = out + (size_t)Bb * Nn * FOUT;             // [4,512,64,64]
    float* w2     = w1 + (size_t)Hh * Bb * Nn * Nn;           // [4,512,64,64]

    float* x1p = nullptr; float* x2p = nullptr;
    cudaGetSymbolAddress((void**)&x1p, g_x1);
    cudaGetSymbolAddress((void**)&x2p, g_x2);

    const int SMEM1 = (64*256 + 64*128 + 128*68 + 64*128 + 64*32 + 2*32*132) * 4;
    const int SMEM2 = (64*128 + 64*128 + 128*68 + 64*128 + 64*32 + 2*32*132) * 4;
    cudaFuncSetAttribute(attn_kernel<256>, cudaFuncAttributeMaxDynamicSharedMemorySize, SMEM1);
    cudaFuncSetAttribute(attn_kernel<128>, cudaFuncAttributeMaxDynamicSharedMemorySize, SMEM2);

    dim3 grid(Hh, Bb);
    attn_kernel<256><<<grid, 512, SMEM1>>>(states, E1w, E1b, K1w, K1b,
                                           Q1w, Q1b, V1w, V1b, w1, x1p);
    attn_kernel<128><<<grid, 512, SMEM2>>>(x1p, E2w, E2b, K2w, K2b,
                                           Q2w, Q2b, V2w, V2b, w2, x2p);
    mlp_kernel<<<512, 256>>>(x2p, F1w, F1b, F2w, F2b, policy);
}

// round 12
// speedup vs baseline: 1.1711x; 1.1711x over previous
#include <cuda_runtime.h>
#include <cstdint>

#define LRELU(v) ((v) > 0.0f ? (v) : 0.01f * (v))
using ull = unsigned long long;

static constexpr int Bb   = 512;
static constexpr int Nn   = 64;
static constexpr int Hh   = 4;
static constexpr int FOUT = 16;

// Scratch
__device__ float g_x1[(size_t)Bb * Nn * 128];
__device__ float g_x2[(size_t)Bb * Nn * 128];
__device__ float g_M [(size_t)2 * Hh * 128 * 128];   // M_h = Qw^T Kw  (stored [d'][d])
__device__ float g_a2[(size_t)2 * Hh * 128];         // a2_h = Kw^T qb
__device__ float g_zero128[128];                     // zero-initialized

// ---------------------------------------------------------------------------
// Packed fp32x2 helpers (Blackwell FFMA2 — PTX only)
// ---------------------------------------------------------------------------
__device__ __forceinline__ ull pack2(float a, float b) {
    ull r; asm("mov.b64 %0, {%1, %2};" : "=l"(r) : "f"(a), "f"(b)); return r;
}
__device__ __forceinline__ void unpack2(ull v, float& a, float& b) {
    asm("mov.b64 {%0, %1}, %2;" : "=f"(a), "=f"(b) : "l"(v));
}
__device__ __forceinline__ ull fma2(ull a, ull b, ull c) {
    ull d; asm("fma.rn.f32x2 %0, %1, %2, %3;" : "=l"(d) : "l"(a), "l"(b), "l"(c)); return d;
}

// ---------------------------------------------------------------------------
// cp.async helpers
// ---------------------------------------------------------------------------
__device__ __forceinline__ uint32_t s2u(const void* p) {
    return (uint32_t)__cvta_generic_to_shared(p);
}
__device__ __forceinline__ void cp4(uint32_t dst, const float* src) {
    asm volatile("cp.async.ca.shared.global [%0], [%1], 4;" :: "r"(dst), "l"(src));
}
__device__ __forceinline__ void cp_commit() {
    asm volatile("cp.async.commit_group;" ::: "memory");
}
template<int N>
__device__ __forceinline__ void cp_wait() {
    asm volatile("cp.async.wait_group %0;" :: "n"(N) : "memory");
}

// ---------------------------------------------------------------------------
// Prep: per head, M[d'][d] = sum_e Kw[e,d']*Qw[e,d] ;  a2[d] = sum_e Kw[e,d]*qb[e]
// grid (4 heads, 8 slices), 256 threads. Qw/Kw are L1-resident (64KB each).
// ---------------------------------------------------------------------------
__global__ void __launch_bounds__(256)
prep_kernel(const float* __restrict__ Qw, const float* __restrict__ Kw,
            const float* __restrict__ Qb, float* __restrict__ Mout,
            float* __restrict__ a2out)
{
    const int h = blockIdx.x, slice = blockIdx.y, tid = threadIdx.x;
    const float* Qh = Qw + (size_t)h * 128 * 128;
    const float* Kh = Kw + (size_t)h * 128 * 128;
#pragma unroll
    for (int j = 0; j < 8; ++j) {
        int id = tid + 256 * j;
        int dp = 16 * slice + (id >> 7);     // warp-uniform
        int d  = id & 127;                   // lane-consecutive
        float s = 0.f;
#pragma unroll 4
        for (int e = 0; e < 128; ++e)
            s += __ldg(&Kh[e * 128 + dp]) * __ldg(&Qh[e * 128 + d]);
        Mout[((size_t)h * 128 + dp) * 128 + d] = s;
    }
    if (slice == 0 && tid < 128) {
        float s = 0.f;
#pragma unroll 4
        for (int e = 0; e < 128; ++e)
            s += __ldg(&Kh[e * 128 + tid]) * __ldg(&Qb[h * 128 + e]);
        a2out[h * 128 + tid] = s;
    }
}

// ---------------------------------------------------------------------------
// Register-blocked packed GEMM: C[64][NC] = A(smem)[64][K] * W(gmem)[NC][K]^T + b
// 256 threads, G col-groups (tx), 256/G row-groups; micro-tile RPT x CW.
//   Main GEMMs: G=32, RPT=8 -> warp-uniform ty, A-loads pure broadcasts,
//   B = one LDS.128 per kk. W staged transposed [kk][n] via dbl-buf cp.async.
// DUALT: epilogue additionally writes a transposed copy (stride ldoT).
// ---------------------------------------------------------------------------
template<int NC, int RPT, int G, bool DUALT>
__device__ __forceinline__ void gemm(
    const float* __restrict__ sA, int lda, int Kdim,
    const float* __restrict__ gW, const float* __restrict__ gBias,
    float* __restrict__ sWt,              // 2 buffers of 32*132 floats
    float* __restrict__ sOut, int ldo, bool relu, int tid,
    float* __restrict__ sOutT, int ldoT)
{
    constexpr int CW    = NC / G;
    constexpr int NPAIR = CW / 2;
    const int tx = tid % G, ty = tid / G;

    ull acc[RPT][NPAIR];
#pragma unroll
    for (int i = 0; i < RPT; ++i)
#pragma unroll
        for (int p = 0; p < NPAIR; ++p) acc[i][p] = 0ull;

    const int kk = tid & 31;
    const int n0 = tid >> 5;               // 0..7
    const int ntiles = Kdim / 32;

    auto stage = [&](int t, int buf) {
        float* dst = sWt + buf * (32 * 132) + kk * 132;
        const float* src = gW + (size_t)t * 32 + kk;
#pragma unroll
        for (int n = n0; n < NC; n += 8)
            cp4(s2u(dst + n), src + (size_t)n * Kdim);
        cp_commit();
    };

    stage(0, 0);
    for (int t = 0; t < ntiles; ++t) {
        if (t + 1 < ntiles) { stage(t + 1, (t + 1) & 1); cp_wait<1>(); }
        else                { cp_wait<0>(); }
        __syncthreads();                   // tile t ready; fences prior phase smem
        const float* w  = sWt + (t & 1) * (32 * 132);
        const float* ar = sA + (RPT * ty) * lda + t * 32;
#pragma unroll
        for (int k4 = 0; k4 < 8; ++k4) {
            float4 a[RPT];
#pragma unroll
            for (int r = 0; r < RPT; ++r)
                a[r] = *(const float4*)(ar + r * lda + 4 * k4);   // broadcast
#pragma unroll
            for (int q = 0; q < 4; ++q) {
                ull ap[RPT];
#pragma unroll
                for (int r = 0; r < RPT; ++r)
                    ap[r] = pack2((&a[r].x)[q], (&a[r].x)[q]);
                const float* brow = w + (4 * k4 + q) * 132 + CW * tx;
                ull bb[NPAIR];
                if constexpr (NPAIR == 2) {
                    ulonglong2 b2 = *(const ulonglong2*)brow;     // LDS.128
                    bb[0] = b2.x; bb[1] = b2.y;
                } else {
                    bb[0] = *(const ull*)brow;                    // LDS.64
                }
#pragma unroll
                for (int r = 0; r < RPT; ++r)
#pragma unroll
                    for (int p = 0; p < NPAIR; ++p)
                        acc[r][p] = fma2(ap[r], bb[p], acc[r][p]);
            }
        }
        __syncthreads();                   // safe to overwrite buffer t&1
    }

    // epilogue
#pragma unroll
    for (int p = 0; p < NPAIR; ++p) {
        int col = CW * tx + 2 * p;
        float b0 = gBias[col], b1 = gBias[col + 1];
#pragma unroll
        for (int i = 0; i < RPT; ++i) {
            float v0, v1; unpack2(acc[i][p], v0, v1);
            v0 += b0; v1 += b1;
            if (relu) { v0 = LRELU(v0); v1 = LRELU(v1); }
            int row = RPT * ty + i;
            *(float2*)&sOut[row * ldo + col] = make_float2(v0, v1);
            if constexpr (DUALT) {
                sOutT[col * ldoT + row]       = v0;
                sOutT[(col + 1) * ldoT + row] = v1;
            }
        }
    }
}

// ---------------------------------------------------------------------------
// Fused attention block with merged QK:
//   se  = lrelu(x Ew^T + Eb)           [64,128]  (+ transposed copy seT)
//   t   = se M^T                        [64,128]  (M = Qw^T Kw)
//   v   = lrelu(se Vw^T + Vb)           [64,32]
//   c_m = se_m . a2   (a2 = Kw^T qb)    [64]
//   w   = softmax((t se^T + c_m)/sqrt(128))  -> w_out  (row-const terms cancel)
//   att = w v  -> x_out
// One CTA (256 threads) per (head h, batch b).
// ---------------------------------------------------------------------------
template<int IN_DIM>
__global__ void __launch_bounds__(256, 1)
attn_kernel(const float* __restrict__ x,
            const float* __restrict__ Ew, const float* __restrict__ Eb,
            const float* __restrict__ gM, const float* __restrict__ gA2,
            const float* __restrict__ Vw, const float* __restrict__ Vb,
            float* __restrict__ w_out, float* __restrict__ x_out)
{
    extern __shared__ float smem[];
    const int h = blockIdx.x, b = blockIdx.y;
    const int tid = threadIdx.x;

    float* s_x   = smem;                    // 64*IN_DIM  (t overlays after phase1)
    float* s_se  = s_x   + 64 * IN_DIM;     // 64*128
    float* s_seT = s_se  + 64 * 128;        // 128*66
    float* s_wt  = s_seT + 128 * 66;        // 2 * 32*132 staging
    float* s_v   = s_wt  + 2 * 32 * 132;    // 64*32
    float* s_w   = s_v   + 64 * 32;         // 64*64
    float* s_c   = s_w   + 64 * 64;         // 64
    float* s_t   = s_x;                     // 64*128 overlay (x dead after phase1)

    // Load input tile x[b]; fenced by gemm's first internal barrier.
    const float* gx = x + (size_t)b * 64 * IN_DIM;
    for (int i = 4 * tid; i < 64 * IN_DIM; i += 1024)
        *(float4*)&s_x[i] = *(const float4*)&gx[i];

    // Phase 1: se (+ seT copy)
    gemm<128, 8, 32, true>(s_x, IN_DIM, IN_DIM,
                           Ew + (size_t)h * 128 * IN_DIM, Eb + h * 128,
                           s_wt, s_se, 128, true, tid, s_seT, 66);
    // Phase 2a: t = se M^T (zero bias, no relu)
    gemm<128, 8, 32, false>(s_se, 128, 128,
                            gM + (size_t)h * 128 * 128, g_zero128,
                            s_wt, s_t, 128, false, tid, nullptr, 0);
    // Phase 2b: v
    gemm<32, 4, 16, false>(s_se, 128, 128,
                           Vw + (size_t)h * 32 * 128, Vb + h * 32,
                           s_wt, s_v, 32, true, tid, nullptr, 0);

    // c_m = se_m . a2  (warp-cooperative; se visible via gemm barriers)
    {
        const int lane = tid & 31, wp = tid >> 5;
        const float* a2h = gA2 + h * 128;
        float av0 = __ldg(&a2h[lane]),      av1 = __ldg(&a2h[lane + 32]);
        float av2 = __ldg(&a2h[lane + 64]), av3 = __ldg(&a2h[lane + 96]);
#pragma unroll
        for (int i = 0; i < 8; ++i) {
            int row = 8 * wp + i;
            const float* sr = s_se + row * 128;
            float p = sr[lane] * av0 + sr[lane + 32] * av1
                    + sr[lane + 64] * av2 + sr[lane + 96] * av3;
#pragma unroll
            for (int off = 16; off > 0; off >>= 1)
                p += __shfl_xor_sync(0xffffffffu, p, off);
            if (lane == 0) s_c[row] = p;
        }
    }
    __syncthreads();

    // Phase 3: scores = t . se^T + c, softmax. Grid 32(tx) x 8(ty): 8 rows.
    {
        const int tx = tid & 31, ty = tid >> 5;
        const float2 cc = *(const float2*)&s_c[2 * tx];
        ull sacc[8];
#pragma unroll
        for (int i = 0; i < 8; ++i) sacc[i] = 0ull;
#pragma unroll 4
        for (int k4 = 0; k4 < 32; ++k4) {
            float4 a[8];
#pragma unroll
            for (int r = 0; r < 8; ++r)
                a[r] = *(const float4*)&s_t[(8 * ty + r) * 128 + 4 * k4];
#pragma unroll
            for (int q = 0; q < 4; ++q) {
                ull bb = *(const ull*)&s_seT[(4 * k4 + q) * 66 + 2 * tx];
#pragma unroll
                for (int r = 0; r < 8; ++r)
                    sacc[r] = fma2(pack2((&a[r].x)[q], (&a[r].x)[q]), bb, sacc[r]);
            }
        }
        const float SCALE = 0.08838834764831845f;  // 1/sqrt(128)
        float* wg = w_out + (((size_t)h * Bb + b) * 64) * 64;
#pragma unroll
        for (int i = 0; i < 8; ++i) {
            float sc0, sc1; unpack2(sacc[i], sc0, sc1);
            sc0 = (sc0 + cc.x) * SCALE;
            sc1 = (sc1 + cc.y) * SCALE;
            float m = fmaxf(sc0, sc1);
#pragma unroll
            for (int off = 1; off < 32; off <<= 1)
                m = fmaxf(m, __shfl_xor_sync(0xffffffffu, m, off));
            sc0 = __expf(sc0 - m); sc1 = __expf(sc1 - m);
            float s = sc0 + sc1;
#pragma unroll
            for (int off = 1; off < 32; off <<= 1)
                s += __shfl_xor_sync(0xffffffffu, s, off);
            float inv = 1.0f / s;
            float2 wv = make_float2(sc0 * inv, sc1 * inv);
            int row = 8 * ty + i;
            *(float2*)&s_w[row * 64 + 2 * tx] = wv;
            *(float2*)&wg[(size_t)row * 64 + 2 * tx] = wv;
        }
    }
    __syncthreads();

    // Phase 4: att = w @ v (64x32, K=64). Grid 16(tx) x 16(ty): 4 rows x 2 cols.
    {
        const int tx = tid & 15, ty = tid >> 4;
        ull aacc[4] = {0ull, 0ull, 0ull, 0ull};
#pragma unroll 4
        for (int k4 = 0; k4 < 16; ++k4) {
            float4 a0 = *(const float4*)&s_w[(4 * ty + 0) * 64 + 4 * k4];
            float4 a1 = *(const float4*)&s_w[(4 * ty + 1) * 64 + 4 * k4];
            float4 a2 = *(const float4*)&s_w[(4 * ty + 2) * 64 + 4 * k4];
            float4 a3 = *(const float4*)&s_w[(4 * ty + 3) * 64 + 4 * k4];
#pragma unroll
            for (int q = 0; q < 4; ++q) {
                ull bb = *(const ull*)&s_v[(4 * k4 + q) * 32 + 2 * tx];
                aacc[0] = fma2(pack2((&a0.x)[q], (&a0.x)[q]), bb, aacc[0]);
                aacc[1] = fma2(pack2((&a1.x)[q], (&a1.x)[q]), bb, aacc[1]);
                aacc[2] = fma2(pack2((&a2.x)[q], (&a2.x)[q]), bb, aacc[2]);
                aacc[3] = fma2(pack2((&a3.x)[q], (&a3.x)[q]), bb, aacc[3]);
            }
        }
#pragma unroll
        for (int i = 0; i < 4; ++i) {
            float v0, v1; unpack2(aacc[i], v0, v1);
            int row = 4 * ty + i;
            *(float2*)&x_out[((size_t)b * 64 + row) * 128 + h * 32 + 2 * tx] =
                make_float2(v0, v1);
        }
    }
}

// ---------------------------------------------------------------------------
// Final MLP + softmax policy head.
// ---------------------------------------------------------------------------
__global__ void __launch_bounds__(256)
mlp_kernel(const float* __restrict__ x,
           const float* __restrict__ F1w, const float* __restrict__ F1b,
           const float* __restrict__ F2w, const float* __restrict__ F2b,
           float* __restrict__ out)
{
    __shared__ float sF1[128 * 65];
    __shared__ float sF2[16 * 64];
    __shared__ float sB1[64];
    __shared__ float sB2[16];
    __shared__ float sx[8][2][128];

    const int tid = threadIdx.x, lane = tid & 31, warp = tid >> 5;

    for (int idx = tid; idx < 64 * 128; idx += 256) {
        int o = idx >> 7, d = idx & 127;
        sF1[d * 65 + o] = F1w[idx];
    }
    for (int idx = tid; idx < 16 * 64; idx += 256) sF2[idx] = F2w[idx];
    if (tid < 64) sB1[tid] = F1b[tid];
    if (tid < 16) sB2[tid] = F2b[tid];
    __syncthreads();

    const int NGRP = (Bb * Nn) / 2;
    for (int g = blockIdx.x * 8 + warp; g < NGRP; g += gridDim.x * 8) {
        int row0 = g * 2;
#pragma unroll
        for (int r = 0; r < 2; ++r)
            *(float4*)&sx[warp][r][lane * 4] =
                *(const float4*)&x[(size_t)(row0 + r) * 128 + lane * 4];
        __syncwarp();

        float h0[2], h1[2];
        h0[0] = h0[1] = sB1[lane];
        h1[0] = h1[1] = sB1[lane + 32];
#pragma unroll 8
        for (int d = 0; d < 128; ++d) {
            float w0 = sF1[d * 65 + lane];
            float w1 = sF1[d * 65 + 32 + lane];
#pragma unroll
            for (int r = 0; r < 2; ++r) {
                float xv = sx[warp][r][d];
                h0[r] = fmaf(xv, w0, h0[r]);
                h1[r] = fmaf(xv, w1, h1[r]);
            }
        }
#pragma unroll
        for (int r = 0; r < 2; ++r) { h0[r] = LRELU(h0[r]); h1[r] = LRELU(h1[r]); }

#pragma unroll
        for (int r = 0; r < 2; ++r) {
            float p[16];
#pragma unroll
            for (int j = 0; j < 16; ++j) {
                float t = fmaf(h0[r], sF2[j * 64 + lane],
                               h1[r] * sF2[j * 64 + 32 + lane]);
#pragma unroll
                for (int off = 16; off > 0; off >>= 1)
                    t += __shfl_xor_sync(0xffffffffu, t, off);
                p[j] = t + sB2[j];
            }
            float m = p[0];
#pragma unroll
            for (int j = 1; j < 16; ++j) m = fmaxf(m, p[j]);
            float s = 0.0f;
#pragma unroll
            for (int j = 0; j < 16; ++j) { p[j] = __expf(p[j] - m); s += p[j]; }
            float inv = 1.0f / s;
            float mine = 0.0f;
#pragma unroll
            for (int j = 0; j < 16; ++j) mine = (lane == j) ? p[j] * inv : mine;
            if (lane < 16) out[(size_t)(row0 + r) * 16 + lane] = mine;
        }
        __syncwarp();
    }
}

// ---------------------------------------------------------------------------
extern "C" void kernel_launch(void* const* d_in, const int* in_sizes, int n_in,
                              void* d_out, int out_size)
{
    const float* states = (const float*)d_in[0];
    const float* E1w = (const float*)d_in[1];  const float* E1b = (const float*)d_in[2];
    const float* K1w = (const float*)d_in[3];  const float* K1b = (const float*)d_in[4];
    const float* Q1w = (const float*)d_in[5];  const float* Q1b = (const float*)d_in[6];
    const float* V1w = (const float*)d_in[7];  const float* V1b = (const float*)d_in[8];
    const float* E2w = (const float*)d_in[9];  const float* E2b = (const float*)d_in[10];
    const float* K2w = (const float*)d_in[11]; const float* K2b = (const float*)d_in[12];
    const float* Q2w = (const float*)d_in[13]; const float* Q2b = (const float*)d_in[14];
    const float* V2w = (const float*)d_in[15]; const float* V2b = (const float*)d_in[16];
    const float* F1w = (const float*)d_in[17]; const float* F1b = (const float*)d_in[18];
    const float* F2w = (const float*)d_in[19]; const float* F2b = (const float*)d_in[20];
    (void)K1b; (void)K2b;   // K biases cancel in softmax (row-constant terms)

    float* out    = (float*)d_out;
    float* policy = out;                                      // [512,64,16]
    float* w1     = out + (size_t)Bb * Nn * FOUT;             // [4,512,64,64]
    float* w2     = w1 + (size_t)Hh * Bb * Nn * Nn;           // [4,512,64,64]

    float* x1p = nullptr; float* x2p = nullptr;
    float* Mp = nullptr;  float* a2p = nullptr;
    cudaGetSymbolAddress((void**)&x1p, g_x1);
    cudaGetSymbolAddress((void**)&x2p, g_x2);
    cudaGetSymbolAddress((void**)&Mp,  g_M);
    cudaGetSymbolAddress((void**)&a2p, g_a2);

    // Prep: M = Qw^T Kw, a2 = Kw^T qb per head, both stages
    prep_kernel<<<dim3(Hh, 8), 256>>>(Q1w, K1w, Q1b, Mp,                a2p);
    prep_kernel<<<dim3(Hh, 8), 256>>>(Q2w, K2w, Q2b, Mp + Hh * 128 * 128, a2p + Hh * 128);

    const int SMEM1 = (64*256 + 64*128 + 128*66 + 2*32*132 + 64*32 + 64*64 + 64) * 4;
    const int SMEM2 = (64*128 + 64*128 + 128*66 + 2*32*132 + 64*32 + 64*64 + 64) * 4;
    cudaFuncSetAttribute(attn_kernel<256>, cudaFuncAttributeMaxDynamicSharedMemorySize, SMEM1);
    cudaFuncSetAttribute(attn_kernel<128>, cudaFuncAttributeMaxDynamicSharedMemorySize, SMEM2);

    dim3 grid(Hh, Bb);
    attn_kernel<256><<<grid, 256, SMEM1>>>(states, E1w, E1b,
                                           Mp, a2p, V1w, V1b, w1, x1p);
    attn_kernel<128><<<grid, 256, SMEM2>>>(x1p, E2w, E2b,
                                           Mp + Hh * 128 * 128, a2p + Hh * 128,
                                           V2w, V2b, w2, x2p);
    mlp_kernel<<<512, 256>>>(x2p, F1w, F1b, F2w, F2b, policy);
}

// round 13
// speedup vs baseline: 1.5172x; 1.2956x over previous
#include <cuda_runtime.h>
#include <cstdint>

#define LRELU(v) ((v) > 0.0f ? (v) : 0.01f * (v))
using ull = unsigned long long;

static constexpr int Bb   = 512;
static constexpr int Nn   = 64;
static constexpr int Hh   = 4;
static constexpr int FOUT = 16;

// Scratch
__device__ float g_x1[(size_t)Bb * Nn * 128];
__device__ float g_x2[(size_t)Bb * Nn * 128];
__device__ float g_M [(size_t)2 * Hh * 128 * 128];   // M_h = Qw^T Kw ([d'][d])
__device__ float g_a2[(size_t)2 * Hh * 128];         // a2_h = Kw^T qb

// ---------------------------------------------------------------------------
// Packed fp32x2 helpers
// ---------------------------------------------------------------------------
__device__ __forceinline__ ull pack2(float a, float b) {
    ull r; asm("mov.b64 %0, {%1, %2};" : "=l"(r) : "f"(a), "f"(b)); return r;
}
__device__ __forceinline__ void unpack2(ull v, float& a, float& b) {
    asm("mov.b64 {%0, %1}, %2;" : "=f"(a), "=f"(b) : "l"(v));
}
__device__ __forceinline__ ull fma2(ull a, ull b, ull c) {
    ull d; asm("fma.rn.f32x2 %0, %1, %2, %3;" : "=l"(d) : "l"(a), "l"(b), "l"(c)); return d;
}

// ---------------------------------------------------------------------------
// cp.async helpers
// ---------------------------------------------------------------------------
__device__ __forceinline__ uint32_t s2u(const void* p) {
    return (uint32_t)__cvta_generic_to_shared(p);
}
__device__ __forceinline__ void cp4(uint32_t dst, const float* src) {
    asm volatile("cp.async.ca.shared.global [%0], [%1], 4;" :: "r"(dst), "l"(src));
}
__device__ __forceinline__ void cp_commit() {
    asm volatile("cp.async.commit_group;" ::: "memory");
}
template<int N>
__device__ __forceinline__ void cp_wait() {
    asm volatile("cp.async.wait_group %0;" :: "n"(N) : "memory");
}

// ---------------------------------------------------------------------------
// Prep: per head, M[d'][d] = sum_e Kw[e,d']*Qw[e,d] ;  a2[d] = sum_e Kw[e,d]*qb[e]
// ---------------------------------------------------------------------------
__global__ void __launch_bounds__(256)
prep_kernel(const float* __restrict__ Qw, const float* __restrict__ Kw,
            const float* __restrict__ Qb, float* __restrict__ Mout,
            float* __restrict__ a2out)
{
    const int h = blockIdx.x, slice = blockIdx.y, tid = threadIdx.x;
    const float* Qh = Qw + (size_t)h * 128 * 128;
    const float* Kh = Kw + (size_t)h * 128 * 128;
#pragma unroll
    for (int j = 0; j < 8; ++j) {
        int id = tid + 256 * j;
        int dp = 16 * slice + (id >> 7);
        int d  = id & 127;
        float s = 0.f;
#pragma unroll 4
        for (int e = 0; e < 128; ++e)
            s += __ldg(&Kh[e * 128 + dp]) * __ldg(&Qh[e * 128 + d]);
        Mout[((size_t)h * 128 + dp) * 128 + d] = s;
    }
    if (slice == 0 && tid < 128) {
        float s = 0.f;
#pragma unroll 4
        for (int e = 0; e < 128; ++e)
            s += __ldg(&Kh[e * 128 + tid]) * __ldg(&Qb[h * 128 + e]);
        a2out[h * 128 + tid] = s;
    }
}

// ---------------------------------------------------------------------------
// Fused attention, 2 CTAs/SM layout (102 KB smem):
//   s_xt  [32][68]   streamed x k-tile, transposed
//   s_seT [128][66]  se^T
//   s_t   [64][128]  t = se M^T
//   s_wt  [128*36]   weight staging (also holds 32*132 tiles; s_w overlays)
//   s_v   [64][32]
//   s_c   [64]
// ---------------------------------------------------------------------------
static constexpr int OFF_XT  = 0;
static constexpr int OFF_SET = OFF_XT  + 32 * 68;     // 2176
static constexpr int OFF_T   = OFF_SET + 128 * 66;    // +8448
static constexpr int OFF_WT  = OFF_T   + 64 * 128;    // +8192
static constexpr int OFF_V   = OFF_WT  + 128 * 36;    // +4608
static constexpr int OFF_C   = OFF_V   + 64 * 32;     // +2048
static constexpr int SMEM_FLOATS = OFF_C + 64;        // 25536 -> 102144 B

template<int IN_DIM>
__global__ void __launch_bounds__(256, 2)
attn_kernel(const float* __restrict__ x,
            const float* __restrict__ Ew, const float* __restrict__ Eb,
            const float* __restrict__ gM, const float* __restrict__ gA2,
            const float* __restrict__ Vw, const float* __restrict__ Vb,
            float* __restrict__ w_out, float* __restrict__ x_out)
{
    extern __shared__ float smem[];
    float* s_xt  = smem + OFF_XT;
    float* s_seT = smem + OFF_SET;
    float* s_t   = smem + OFF_T;
    float* s_wt  = smem + OFF_WT;
    float* s_v   = smem + OFF_V;
    float* s_c   = smem + OFF_C;
    float* s_w   = s_wt;                 // overlay after phase 2b

    const int h = blockIdx.x, b = blockIdx.y, tid = threadIdx.x;
    const float* gx  = x + (size_t)b * 64 * IN_DIM;
    const float* Ewh = Ew + (size_t)h * 128 * IN_DIM;

    // ---- Phase 1: seT[d][n] = lrelu(x Ew^T + Eb)^T ------------------------
    {
        const int tx = tid & 15, ty = tid >> 4;     // 16 n-quads x 16 d-groups
        ull acc[8][2] = {};
        float rx[8];
        auto ldx = [&](int t) {
#pragma unroll
            for (int j = 0; j < 8; ++j) {
                int idx = tid + 256 * j;
                rx[j] = __ldg(&gx[(idx >> 5) * IN_DIM + t * 32 + (idx & 31)]);
            }
        };
        auto stx = [&]() {
#pragma unroll
            for (int j = 0; j < 8; ++j) {
                int idx = tid + 256 * j;
                s_xt[(idx & 31) * 68 + (idx >> 5)] = rx[j];
            }
        };
        auto stageE = [&](int t) {
            for (int idx = tid; idx < 4096; idx += 256) {
                int d = idx >> 5, kk = idx & 31;
                cp4(s2u(s_wt + d * 36 + kk), Ewh + (size_t)d * IN_DIM + t * 32 + kk);
            }
            cp_commit();
        };
        ldx(0); stageE(0);
        const int NT = IN_DIM / 32;
        for (int t = 0; t < NT; ++t) {
            cp_wait<0>(); __syncthreads();          // Ew tile ready, s_xt free
            stx();
            if (t + 1 < NT) ldx(t + 1);
            __syncthreads();                        // x tile visible
#pragma unroll
            for (int k4 = 0; k4 < 8; ++k4) {
                float4 a[8];
#pragma unroll
                for (int r = 0; r < 8; ++r)
                    a[r] = *(const float4*)&s_wt[(8 * ty + r) * 36 + 4 * k4];
#pragma unroll
                for (int q = 0; q < 4; ++q) {
                    ulonglong2 bb = *(const ulonglong2*)&s_xt[(4 * k4 + q) * 68 + 4 * tx];
#pragma unroll
                    for (int r = 0; r < 8; ++r) {
                        ull ap = pack2((&a[r].x)[q], (&a[r].x)[q]);
                        acc[r][0] = fma2(ap, bb.x, acc[r][0]);
                        acc[r][1] = fma2(ap, bb.y, acc[r][1]);
                    }
                }
            }
            __syncthreads();                        // compute done, s_wt free
            if (t + 1 < NT) stageE(t + 1);
        }
#pragma unroll
        for (int r = 0; r < 8; ++r) {
            int d = 8 * ty + r;
            float bias = __ldg(&Eb[h * 128 + d]);
            float v0, v1, v2, v3;
            unpack2(acc[r][0], v0, v1); unpack2(acc[r][1], v2, v3);
            v0 += bias; v1 += bias; v2 += bias; v3 += bias;
            v0 = LRELU(v0); v1 = LRELU(v1); v2 = LRELU(v2); v3 = LRELU(v3);
            *(float2*)&s_seT[d * 66 + 4 * tx]     = make_float2(v0, v1);
            *(float2*)&s_seT[d * 66 + 4 * tx + 2] = make_float2(v2, v3);
        }
    }

    // ---- Phase 2a: t[n][d'] = se M^T (A from seT scalar broadcasts) -------
    {
        const int tx = tid & 31, ty = tid >> 5;     // 32 d'-quads x 8 n-groups
        ull acc[8][2] = {};
        const float* gMh = gM + (size_t)h * 128 * 128;
        auto stageM = [&](int t) {
            for (int idx = tid; idx < 4096; idx += 256) {
                int n = idx >> 5, kk = idx & 31;
                cp4(s2u(s_wt + kk * 132 + n), gMh + (size_t)n * 128 + t * 32 + kk);
            }
            cp_commit();
        };
        stageM(0);
        for (int t = 0; t < 4; ++t) {
            cp_wait<0>(); __syncthreads();          // (also orders seT stores)
#pragma unroll
            for (int k4 = 0; k4 < 8; ++k4) {
#pragma unroll
                for (int q = 0; q < 4; ++q) {
                    const float* sa = &s_seT[(t * 32 + 4 * k4 + q) * 66 + 8 * ty];
                    ulonglong2 bb = *(const ulonglong2*)&s_wt[(4 * k4 + q) * 132 + 4 * tx];
#pragma unroll
                    for (int r = 0; r < 8; ++r) {
                        float av = sa[r];
                        ull ap = pack2(av, av);
                        acc[r][0] = fma2(ap, bb.x, acc[r][0]);
                        acc[r][1] = fma2(ap, bb.y, acc[r][1]);
                    }
                }
            }
            __syncthreads();
            if (t + 1 < 4) stageM(t + 1);
        }
#pragma unroll
        for (int r = 0; r < 8; ++r) {
            int row = 8 * ty + r;
            float v0, v1, v2, v3;
            unpack2(acc[r][0], v0, v1); unpack2(acc[r][1], v2, v3);
            *(float2*)&s_t[row * 128 + 4 * tx]     = make_float2(v0, v1);
            *(float2*)&s_t[row * 128 + 4 * tx + 2] = make_float2(v2, v3);
        }
    }

    // ---- Phase 2b: v[m][o] = lrelu(se Vw^T + Vb) ---------------------------
    {
        const int tx = tid & 15, ty = tid >> 4;     // 16 o-pairs x 16 m-groups
        ull acc[4] = {};
        const float* Vwh = Vw + (size_t)h * 32 * 128;
        auto stageV = [&](int t) {
            for (int idx = tid; idx < 1024; idx += 256) {
                int n = idx >> 5, kk = idx & 31;
                cp4(s2u(s_wt + kk * 132 + n), Vwh + (size_t)n * 128 + t * 32 + kk);
            }
            cp_commit();
        };
        stageV(0);
        for (int t = 0; t < 4; ++t) {
            cp_wait<0>(); __syncthreads();
#pragma unroll
            for (int k4 = 0; k4 < 8; ++k4) {
#pragma unroll
                for (int q = 0; q < 4; ++q) {
                    const float* sa = &s_seT[(t * 32 + 4 * k4 + q) * 66 + 4 * ty];
                    ull bb = *(const ull*)&s_wt[(4 * k4 + q) * 132 + 2 * tx];
#pragma unroll
                    for (int r = 0; r < 4; ++r) {
                        float av = sa[r];
                        acc[r] = fma2(pack2(av, av), bb, acc[r]);
                    }
                }
            }
            __syncthreads();
            if (t + 1 < 4) stageV(t + 1);
        }
        float b0 = __ldg(&Vb[h * 32 + 2 * tx]), b1 = __ldg(&Vb[h * 32 + 2 * tx + 1]);
#pragma unroll
        for (int r = 0; r < 4; ++r) {
            float v0, v1; unpack2(acc[r], v0, v1);
            v0 += b0; v1 += b1; v0 = LRELU(v0); v1 = LRELU(v1);
            *(float2*)&s_v[(4 * ty + r) * 32 + 2 * tx] = make_float2(v0, v1);
        }
    }

    // ---- c_m = se_m . a2 ----------------------------------------------------
    if (tid < 64) {
        const float* a2h = gA2 + h * 128;
        float s = 0.f;
#pragma unroll 4
        for (int d = 0; d < 128; ++d)
            s += s_seT[d * 66 + tid] * __ldg(&a2h[d]);
        s_c[tid] = s;
    }
    __syncthreads();

    // ---- Phase 3: scores = t . seT + c, softmax ----------------------------
    {
        const int tx = tid & 31, ty = tid >> 5;
        const float2 cc = *(const float2*)&s_c[2 * tx];
        ull sacc[8] = {};
#pragma unroll 4
        for (int k4 = 0; k4 < 32; ++k4) {
            float4 a[8];
#pragma unroll
            for (int r = 0; r < 8; ++r)
                a[r] = *(const float4*)&s_t[(8 * ty + r) * 128 + 4 * k4];
#pragma unroll
            for (int q = 0; q < 4; ++q) {
                ull bb = *(const ull*)&s_seT[(4 * k4 + q) * 66 + 2 * tx];
#pragma unroll
                for (int r = 0; r < 8; ++r)
                    sacc[r] = fma2(pack2((&a[r].x)[q], (&a[r].x)[q]), bb, sacc[r]);
            }
        }
        const float SCALE = 0.08838834764831845f;   // 1/sqrt(128)
        float* wg = w_out + (((size_t)h * Bb + b) * 64) * 64;
#pragma unroll
        for (int i = 0; i < 8; ++i) {
            float sc0, sc1; unpack2(sacc[i], sc0, sc1);
            sc0 = (sc0 + cc.x) * SCALE;
            sc1 = (sc1 + cc.y) * SCALE;
            float m = fmaxf(sc0, sc1);
#pragma unroll
            for (int off = 1; off < 32; off <<= 1)
                m = fmaxf(m, __shfl_xor_sync(0xffffffffu, m, off));
            sc0 = __expf(sc0 - m); sc1 = __expf(sc1 - m);
            float s = sc0 + sc1;
#pragma unroll
            for (int off = 1; off < 32; off <<= 1)
                s += __shfl_xor_sync(0xffffffffu, s, off);
            float inv = 1.0f / s;
            float2 wv = make_float2(sc0 * inv, sc1 * inv);
            int row = 8 * ty + i;
            *(float2*)&s_w[row * 64 + 2 * tx] = wv;
            *(float2*)&wg[(size_t)row * 64 + 2 * tx] = wv;
        }
    }
    __syncthreads();

    // ---- Phase 4: att = w @ v ----------------------------------------------
    {
        const int tx = tid & 15, ty = tid >> 4;
        ull aacc[4] = {};
#pragma unroll 4
        for (int k4 = 0; k4 < 16; ++k4) {
            float4 a0 = *(const float4*)&s_w[(4 * ty + 0) * 64 + 4 * k4];
            float4 a1 = *(const float4*)&s_w[(4 * ty + 1) * 64 + 4 * k4];
            float4 a2 = *(const float4*)&s_w[(4 * ty + 2) * 64 + 4 * k4];
            float4 a3 = *(const float4*)&s_w[(4 * ty + 3) * 64 + 4 * k4];
#pragma unroll
            for (int q = 0; q < 4; ++q) {
                ull bb = *(const ull*)&s_v[(4 * k4 + q) * 32 + 2 * tx];
                aacc[0] = fma2(pack2((&a0.x)[q], (&a0.x)[q]), bb, aacc[0]);
                aacc[1] = fma2(pack2((&a1.x)[q], (&a1.x)[q]), bb, aacc[1]);
                aacc[2] = fma2(pack2((&a2.x)[q], (&a2.x)[q]), bb, aacc[2]);
                aacc[3] = fma2(pack2((&a3.x)[q], (&a3.x)[q]), bb, aacc[3]);
            }
        }
#pragma unroll
        for (int i = 0; i < 4; ++i) {
            float v0, v1; unpack2(aacc[i], v0, v1);
            int row = 4 * ty + i;
            *(float2*)&x_out[((size_t)b * 64 + row) * 128 + h * 32 + 2 * tx] =
                make_float2(v0, v1);
        }
    }
}

// ---------------------------------------------------------------------------
// Final MLP + softmax policy head.
// ---------------------------------------------------------------------------
__global__ void __launch_bounds__(256)
mlp_kernel(const float* __restrict__ x,
           const float* __restrict__ F1w, const float* __restrict__ F1b,
           const float* __restrict__ F2w, const float* __restrict__ F2b,
           float* __restrict__ out)
{
    __shared__ float sF1[128 * 65];
    __shared__ float sF2[16 * 64];
    __shared__ float sB1[64];
    __shared__ float sB2[16];
    __shared__ float sx[8][2][128];

    const int tid = threadIdx.x, lane = tid & 31, warp = tid >> 5;

    for (int idx = tid; idx < 64 * 128; idx += 256) {
        int o = idx >> 7, d = idx & 127;
        sF1[d * 65 + o] = F1w[idx];
    }
    for (int idx = tid; idx < 16 * 64; idx += 256) sF2[idx] = F2w[idx];
    if (tid < 64) sB1[tid] = F1b[tid];
    if (tid < 16) sB2[tid] = F2b[tid];
    __syncthreads();

    const int NGRP = (Bb * Nn) / 2;
    for (int g = blockIdx.x * 8 + warp; g < NGRP; g += gridDim.x * 8) {
        int row0 = g * 2;
#pragma unroll
        for (int r = 0; r < 2; ++r)
            *(float4*)&sx[warp][r][lane * 4] =
                *(const float4*)&x[(size_t)(row0 + r) * 128 + lane * 4];
        __syncwarp();

        float h0[2], h1[2];
        h0[0] = h0[1] = sB1[lane];
        h1[0] = h1[1] = sB1[lane + 32];
#pragma unroll 8
        for (int d = 0; d < 128; ++d) {
            float w0 = sF1[d * 65 + lane];
            float w1 = sF1[d * 65 + 32 + lane];
#pragma unroll
            for (int r = 0; r < 2; ++r) {
                float xv = sx[warp][r][d];
                h0[r] = fmaf(xv, w0, h0[r]);
                h1[r] = fmaf(xv, w1, h1[r]);
            }
        }
#pragma unroll
        for (int r = 0; r < 2; ++r) { h0[r] = LRELU(h0[r]); h1[r] = LRELU(h1[r]); }

#pragma unroll
        for (int r = 0; r < 2; ++r) {
            float p[16];
#pragma unroll
            for (int j = 0; j < 16; ++j) {
                float t = fmaf(h0[r], sF2[j * 64 + lane],
                               h1[r] * sF2[j * 64 + 32 + lane]);
#pragma unroll
                for (int off = 16; off > 0; off >>= 1)
                    t += __shfl_xor_sync(0xffffffffu, t, off);
                p[j] = t + sB2[j];
            }
            float m = p[0];
#pragma unroll
            for (int j = 1; j < 16; ++j) m = fmaxf(m, p[j]);
            float s = 0.0f;
#pragma unroll
            for (int j = 0; j < 16; ++j) { p[j] = __expf(p[j] - m); s += p[j]; }
            float inv = 1.0f / s;
            float mine = 0.0f;
#pragma unroll
            for (int j = 0; j < 16; ++j) mine = (lane == j) ? p[j] * inv : mine;
            if (lane < 16) out[(size_t)(row0 + r) * 16 + lane] = mine;
        }
        __syncwarp();
    }
}

// ---------------------------------------------------------------------------
extern "C" void kernel_launch(void* const* d_in, const int* in_sizes, int n_in,
                              void* d_out, int out_size)
{
    const float* states = (const float*)d_in[0];
    const float* E1w = (const float*)d_in[1];  const float* E1b = (const float*)d_in[2];
    const float* K1w = (const float*)d_in[3];  const float* K1b = (const float*)d_in[4];
    const float* Q1w = (const float*)d_in[5];  const float* Q1b = (const float*)d_in[6];
    const float* V1w = (const float*)d_in[7];  const float* V1b = (const float*)d_in[8];
    const float* E2w = (const float*)d_in[9];  const float* E2b = (const float*)d_in[10];
    const float* K2w = (const float*)d_in[11]; const float* K2b = (const float*)d_in[12];
    const float* Q2w = (const float*)d_in[13]; const float* Q2b = (const float*)d_in[14];
    const float* V2w = (const float*)d_in[15]; const float* V2b = (const float*)d_in[16];
    const float* F1w = (const float*)d_in[17]; const float* F1b = (const float*)d_in[18];
    const float* F2w = (const float*)d_in[19]; const float* F2b = (const float*)d_in[20];
    (void)K1b; (void)K2b;   // K biases cancel in softmax

    float* out    = (float*)d_out;
    float* policy = out;                                      // [512,64,16]
    float* w1     = out + (size_t)Bb * Nn * FOUT;             // [4,512,64,64]
    float* w2     = w1 + (size_t)Hh * Bb * Nn * Nn;           // [4,512,64,64]

    float* x1p = nullptr; float* x2p = nullptr;
    float* Mp = nullptr;  float* a2p = nullptr;
    cudaGetSymbolAddress((void**)&x1p, g_x1);
    cudaGetSymbolAddress((void**)&x2p, g_x2);
    cudaGetSymbolAddress((void**)&Mp,  g_M);
    cudaGetSymbolAddress((void**)&a2p, g_a2);

    prep_kernel<<<dim3(Hh, 8), 256>>>(Q1w, K1w, Q1b, Mp,                  a2p);
    prep_kernel<<<dim3(Hh, 8), 256>>>(Q2w, K2w, Q2b, Mp + Hh * 128 * 128, a2p + Hh * 128);

    const int SMEM = SMEM_FLOATS * 4;   // 102144 B -> 2 CTAs/SM
    cudaFuncSetAttribute(attn_kernel<256>, cudaFuncAttributeMaxDynamicSharedMemorySize, SMEM);
    cudaFuncSetAttribute(attn_kernel<128>, cudaFuncAttributeMaxDynamicSharedMemorySize, SMEM);

    dim3 grid(Hh, Bb);
    attn_kernel<256><<<grid, 256, SMEM>>>(states, E1w, E1b,
                                          Mp, a2p, V1w, V1b, w1, x1p);
    attn_kernel<128><<<grid, 256, SMEM>>>(x1p, E2w, E2b,
                                          Mp + Hh * 128 * 128, a2p + Hh * 128,
                                          V2w, V2b, w2, x2p);
    mlp_kernel<<<512, 256>>>(x2p, F1w, F1b, F2w, F2b, policy);
}